// round 5
// baseline (speedup 1.0000x reference)
#include <cuda_runtime.h>
#include <cuda_bf16.h>
#include <cstdint>

// ============================================================================
// QConv2D quantum conv via baseline-PTX bf16 mma.sync (HMMA) GEMM.
//   Circuit -> fixed 64x64 complex unitary U (kernel 1, parallel).
//   B[128x64] rows interleaved: B[2s]=Re U[s,:], B[2s+1]=Im U[s,:] (bf16 hi/lo).
//   Kernel 2: persistent-ish CTA, 6 tiles x 64 patches. Per tile:
//   C[64x128] = Ah*Bh^T + Ah*Bl^T + Al*Bh^T (fp32 accum), probs, Walsh sums,
//   deferred normalization. Next tile's x prefetched into regs during GEMM.
// ============================================================================

#define N_QUBITS 6
#define OH 63
#define OHW 3969
#define NPATCH (128 * OHW)     // 508032
#define TILE 64
#define TPC 6                  // tiles per CTA
#define GRID 1323              // 1323 * 6 * 64 = 508032
#define SWZ(o) ((o) ^ (((o) >> 3) & 0x70))

__device__ __nv_bfloat16 g_Bh[128 * 64];
__device__ __nv_bfloat16 g_Bl[128 * 64];

__device__ __forceinline__ uint32_t smem_u32(const void* p) {
    uint32_t a;
    asm("{ .reg .u64 t; cvta.to.shared.u64 t, %1; cvt.u32.u64 %0, t; }"
        : "=r"(a) : "l"(p));
    return a;
}
__device__ __forceinline__ void ldmx4(uint32_t* r, uint32_t addr) {
    asm volatile("ldmatrix.sync.aligned.m8n8.x4.shared.b16 {%0,%1,%2,%3}, [%4];"
                 : "=r"(r[0]), "=r"(r[1]), "=r"(r[2]), "=r"(r[3]) : "r"(addr));
}
__device__ __forceinline__ void mma_bf16(float* c, const uint32_t* a, const uint32_t* b) {
    asm volatile(
        "mma.sync.aligned.m16n8k16.row.col.f32.bf16.bf16.f32 "
        "{%0,%1,%2,%3}, {%4,%5,%6,%7}, {%8,%9}, {%0,%1,%2,%3};"
        : "+f"(c[0]), "+f"(c[1]), "+f"(c[2]), "+f"(c[3])
        : "r"(a[0]), "r"(a[1]), "r"(a[2]), "r"(a[3]), "r"(b[0]), "r"(b[1]));
}

// ----------------------------------------------------------------------------
// Kernel 1: build U; emit B interleaved (Re/Im per state) as bf16 hi/lo.
// ----------------------------------------------------------------------------
__global__ __launch_bounds__(256) void build_unitary_kernel(const float* __restrict__ w) {
    __shared__ float2 S[16][64];
    __shared__ float gt[12][8];
    int t = threadIdx.x;
    int cl = t >> 4;
    int k  = t & 15;

    if (t < 12) {
        int l = t / 6, q = t % 6;
        float phi   = w[(l * 6 + q) * 3 + 0];
        float theta = w[(l * 6 + q) * 3 + 1];
        float omega = w[(l * 6 + q) * 3 + 2];
        float s2, c2; sincosf(0.5f * theta, &s2, &c2);
        float sap, cap; sincosf(-0.5f * (phi + omega), &sap, &cap);
        float sam, cam; sincosf(-0.5f * (phi - omega), &sam, &cam);
        gt[t][0] =  cap * c2; gt[t][1] =  sap * c2;
        gt[t][2] = -cam * s2; gt[t][3] =  sam * s2;
        gt[t][4] =  cam * s2; gt[t][5] =  sam * s2;
        gt[t][6] =  cap * c2; gt[t][7] = -sap * c2;
    }
    int c = blockIdx.x * 16 + cl;
    #pragma unroll
    for (int i = k; i < 64; i += 16) S[cl][i] = make_float2(i == c ? 1.f : 0.f, 0.f);
    __syncthreads();

    for (int rep = 0; rep < 2; rep++) {
        for (int l = 0; l < 2; l++) {
            for (int q = 0; q < N_QUBITS; q++) {
                const float* g = gt[l * 6 + q];
                float u00x = g[0], u00y = g[1], u01x = g[2], u01y = g[3];
                float u10x = g[4], u10y = g[5], u11x = g[6], u11y = g[7];
                int m = 1 << (5 - q);
                #pragma unroll
                for (int pp = 0; pp < 2; pp++) {
                    int pi = k + pp * 16;
                    int i = ((pi & ~(m - 1)) << 1) | (pi & (m - 1));
                    float2 a = S[cl][i], b = S[cl][i | m];
                    float2 na, nb;
                    na.x = u00x * a.x - u00y * a.y + u01x * b.x - u01y * b.y;
                    na.y = u00x * a.y + u00y * a.x + u01x * b.y + u01y * b.x;
                    nb.x = u10x * a.x - u10y * a.y + u11x * b.x - u11y * b.y;
                    nb.y = u10x * a.y + u10y * a.x + u11x * b.y + u11y * b.x;
                    S[cl][i] = na; S[cl][i | m] = nb;
                }
                __syncthreads();
            }
            int r = (l % (N_QUBITS - 1)) + 1;
            for (int q = 0; q < N_QUBITS; q++) {
                int tq = (q + r) % N_QUBITS;
                int mc = 1 << (5 - q);
                int mt = 1 << (5 - tq);
                int i = 0, kk = k;
                #pragma unroll
                for (int b = 0; b < 6; b++) {
                    int bit = 1 << b;
                    if (bit == mc)      i |= bit;
                    else if (bit == mt) { }
                    else { if (kk & 1) i |= bit; kk >>= 1; }
                }
                float2 tmp = S[cl][i];
                S[cl][i] = S[cl][i | mt];
                S[cl][i | mt] = tmp;
                __syncthreads();
            }
        }
    }
    for (int it = t; it < 128 * 16; it += 256) {
        int n  = it >> 4;
        int kl = it & 15;
        int s  = n >> 1;
        float v = (n & 1) ? S[kl][s].y : S[kl][s].x;
        __nv_bfloat16 hi = __float2bfloat16(v);
        __nv_bfloat16 lo = __float2bfloat16(v - __bfloat162float(hi));
        int kg = blockIdx.x * 16 + kl;
        g_Bh[n * 64 + kg] = hi;
        g_Bl[n * 64 + kg] = lo;
    }
}

// ----------------------------------------------------------------------------
// Kernel 2
// ----------------------------------------------------------------------------
#define SM_AH   0          //  8 KB: 64 rows x 128 B
#define SM_AL   8192       //  8 KB
#define SM_BH   16384      // 16 KB: 128 rows x 128 B
#define SM_BL   32768      // 16 KB
#define SM_SSQ  49152      // float[2][64]  = 512 B
#define SM_SZ   49664      // float[2][64][6] = 3072 B
#define SM_TOTAL 52736

__global__ __launch_bounds__(256, 3)
void qconv_kernel(const float* __restrict__ x, float* __restrict__ out) {
    extern __shared__ char smem[];
    const uint32_t sb = smem_u32(smem);
    float* sSsq = reinterpret_cast<float*>(smem + SM_SSQ);   // [buf][64]
    float* sZ   = reinterpret_cast<float*>(smem + SM_SZ);    // [ni][64][6]
    const int tid = threadIdx.x;
    const int L   = tid & 31;
    const int wid = tid >> 5;
    const int mi  = wid >> 1;         // 0..3 (16-row slab)
    const int ni  = wid & 1;          // 0..1 (64-col half)
    const int g   = L >> 2;
    const int qd  = L & 3;

    const int p_l = tid >> 2;         // patch within tile, 0..63
    const int ch  = tid & 3;          // channel 0..3
    const int tileBase = blockIdx.x * (TPC * TILE);

    // ---- stage B (hi/lo) once ----
    {
        const uint4* bh = reinterpret_cast<const uint4*>(g_Bh);
        const uint4* bl = reinterpret_cast<const uint4*>(g_Bl);
        #pragma unroll
        for (int it = 0; it < 4; it++) {
            int idx = tid + it * 256;
            uint32_t off = SWZ((uint32_t)(idx * 16));
            *reinterpret_cast<uint4*>(smem + SM_BH + off) = bh[idx];
            *reinterpret_cast<uint4*>(smem + SM_BL + off) = bl[idx];
        }
    }

    // ---- x load helper state ----
    float2 v[8];

    // load tile 0
    {
        const int pi  = tileBase + p_l;
        const int b   = pi / OHW;
        const int rem = pi - b * OHW;
        const int oy  = rem / OH;
        const int ox  = rem - oy * OH;
        const float* xp = x + (((b * 4 + ch) * 128) + 2 * oy) * 128 + 2 * ox;
        #pragma unroll
        for (int ky = 0; ky < 4; ky++) {
            v[2 * ky + 0] = *reinterpret_cast<const float2*>(xp + ky * 128);
            v[2 * ky + 1] = *reinterpret_cast<const float2*>(xp + ky * 128 + 2);
        }
    }
    // convert tile 0 -> A smem, ssq buf 0
    {
        float ssq = 0.f;
        uint32_t hw[8], lw[8];
        #pragma unroll
        for (int j = 0; j < 8; j++) {
            float va = v[j].x, vb = v[j].y;
            ssq += va * va + vb * vb;
            __nv_bfloat16 ah = __float2bfloat16(va);
            __nv_bfloat16 bh = __float2bfloat16(vb);
            __nv_bfloat16 al = __float2bfloat16(va - __bfloat162float(ah));
            __nv_bfloat16 bl = __float2bfloat16(vb - __bfloat162float(bh));
            __nv_bfloat162 hp = {ah, bh}, lp = {al, bl};
            hw[j] = *reinterpret_cast<uint32_t*>(&hp);
            lw[j] = *reinterpret_cast<uint32_t*>(&lp);
        }
        ssq += __shfl_xor_sync(0xffffffffu, ssq, 1);
        ssq += __shfl_xor_sync(0xffffffffu, ssq, 2);
        if (ch == 0) sSsq[p_l] = ssq;
        uint32_t o0 = SWZ((uint32_t)(p_l * 128 + ch * 32));
        uint32_t o1 = SWZ((uint32_t)(p_l * 128 + ch * 32 + 16));
        *reinterpret_cast<uint4*>(smem + SM_AH + o0) = make_uint4(hw[0], hw[1], hw[2], hw[3]);
        *reinterpret_cast<uint4*>(smem + SM_AH + o1) = make_uint4(hw[4], hw[5], hw[6], hw[7]);
        *reinterpret_cast<uint4*>(smem + SM_AL + o0) = make_uint4(lw[0], lw[1], lw[2], lw[3]);
        *reinterpret_cast<uint4*>(smem + SM_AL + o1) = make_uint4(lw[4], lw[5], lw[6], lw[7]);
    }
    __syncthreads();

    // ---- fragment addresses (constant across tiles) ----
    const uint32_t aAddrBase[2] = {
        sb + SM_AH, sb + SM_AL };
    const uint32_t aRowOff = (uint32_t)((mi * 16 + (L & 15)) * 128);
    const uint32_t aChOff  = (uint32_t)(((L >> 4) & 1) * 16);
    const uint32_t bRowOff = (uint32_t)((ni * 64 + (L & 7) + (((L >> 4) & 1) << 3)) * 128);
    const uint32_t bChOff  = (uint32_t)(((L >> 3) & 1) * 16);

    for (int t = 0; t < TPC; t++) {
        // ---- prefetch next tile's x into regs ----
        if (t + 1 < TPC) {
            const int pi  = tileBase + (t + 1) * TILE + p_l;
            const int b   = pi / OHW;
            const int rem = pi - b * OHW;
            const int oy  = rem / OH;
            const int ox  = rem - oy * OH;
            const float* xp = x + (((b * 4 + ch) * 128) + 2 * oy) * 128 + 2 * ox;
            #pragma unroll
            for (int ky = 0; ky < 4; ky++) {
                v[2 * ky + 0] = *reinterpret_cast<const float2*>(xp + ky * 128);
                v[2 * ky + 1] = *reinterpret_cast<const float2*>(xp + ky * 128 + 2);
            }
        }

        // ---- GEMM ----
        float acc[8][4];
        #pragma unroll
        for (int nt = 0; nt < 8; nt++)
            #pragma unroll
            for (int r = 0; r < 4; r++) acc[nt][r] = 0.f;

        #pragma unroll
        for (int k = 0; k < 4; k++) {
            uint32_t ah[4], al[4];
            uint32_t aoff = SWZ(aRowOff + (uint32_t)(2 * k) * 16 + aChOff);
            ldmx4(ah, aAddrBase[0] + aoff);
            ldmx4(al, aAddrBase[1] + aoff);
            #pragma unroll
            for (int bt = 0; bt < 4; bt++) {
                uint32_t boff = SWZ(bRowOff + (uint32_t)(bt * 16) * 128 +
                                    (uint32_t)(2 * k) * 16 + bChOff);
                uint32_t bh[4], bl[4];
                ldmx4(bh, sb + SM_BH + boff);
                ldmx4(bl, sb + SM_BL + boff);
                #pragma unroll
                for (int n2 = 0; n2 < 2; n2++) {
                    int nt = bt * 2 + n2;
                    mma_bf16(acc[nt], ah, bh + 2 * n2);
                    mma_bf16(acc[nt], ah, bl + 2 * n2);
                    mma_bf16(acc[nt], al, bh + 2 * n2);
                }
            }
        }

        // ---- epilogue: state s = 32ni + 4nt + qd ----
        #pragma unroll
        for (int rh = 0; rh < 2; rh++) {
            float pr[8];
            #pragma unroll
            for (int nt = 0; nt < 8; nt++) {
                float re = acc[nt][rh * 2 + 0];
                float im = acc[nt][rh * 2 + 1];
                pr[nt] = re * re + im * im;
            }
            float qt = 0.f, z1 = 0.f, z2 = 0.f, z3 = 0.f;
            #pragma unroll
            for (int nt = 0; nt < 8; nt++) {
                qt += pr[nt];
                z1 += (nt & 4) ? -pr[nt] : pr[nt];
                z2 += (nt & 2) ? -pr[nt] : pr[nt];
                z3 += (nt & 1) ? -pr[nt] : pr[nt];
            }
            float z0 = qt;
            float z4 = (qd & 2) ? -qt : qt;
            float z5 = (qd & 1) ? -qt : qt;
            #pragma unroll
            for (int o = 1; o <= 2; o <<= 1) {
                z0 += __shfl_xor_sync(0xffffffffu, z0, o);
                z1 += __shfl_xor_sync(0xffffffffu, z1, o);
                z2 += __shfl_xor_sync(0xffffffffu, z2, o);
                z3 += __shfl_xor_sync(0xffffffffu, z3, o);
                z4 += __shfl_xor_sync(0xffffffffu, z4, o);
                z5 += __shfl_xor_sync(0xffffffffu, z5, o);
            }
            if (qd == 0) {
                int row = mi * 16 + rh * 8 + g;
                float* dst = sZ + (ni * 64 + row) * 6;
                dst[0] = z0; dst[1] = z1; dst[2] = z2;
                dst[3] = z3; dst[4] = z4; dst[5] = z5;
            }
        }
        __syncthreads();

        // ---- merge halves + normalize + store (384 outputs) ----
        {
            const float* ssqB = sSsq + (t & 1) * 64;
            #pragma unroll
            for (int half = 0; half < 2; half++) {
                int idx = tid + half * 256;
                if (idx < 384) {
                    int qb  = idx >> 6;       // 0..5
                    int row = idx & 63;
                    int pi  = tileBase + t * TILE + row;
                    int b   = pi / OHW;
                    int rem = pi - b * OHW;
                    float inv = 1.f / ssqB[row];
                    float a0 = sZ[row * 6 + qb];
                    float a1 = sZ[(64 + row) * 6 + qb];
                    float zv = (qb == 0) ? (a0 - a1) : (a0 + a1);
                    out[(b * 6 + qb) * OHW + rem] = zv * inv;
                }
            }
        }

        // ---- convert prefetched tile -> A smem, ssq buf (t+1)&1 ----
        if (t + 1 < TPC) {
            float ssq = 0.f;
            uint32_t hw[8], lw[8];
            #pragma unroll
            for (int j = 0; j < 8; j++) {
                float va = v[j].x, vb = v[j].y;
                ssq += va * va + vb * vb;
                __nv_bfloat16 ah = __float2bfloat16(va);
                __nv_bfloat16 bh = __float2bfloat16(vb);
                __nv_bfloat16 al = __float2bfloat16(va - __bfloat162float(ah));
                __nv_bfloat16 bl = __float2bfloat16(vb - __bfloat162float(bh));
                __nv_bfloat162 hp = {ah, bh}, lp = {al, bl};
                hw[j] = *reinterpret_cast<uint32_t*>(&hp);
                lw[j] = *reinterpret_cast<uint32_t*>(&lp);
            }
            ssq += __shfl_xor_sync(0xffffffffu, ssq, 1);
            ssq += __shfl_xor_sync(0xffffffffu, ssq, 2);
            if (ch == 0) sSsq[((t + 1) & 1) * 64 + p_l] = ssq;
            uint32_t o0 = SWZ((uint32_t)(p_l * 128 + ch * 32));
            uint32_t o1 = SWZ((uint32_t)(p_l * 128 + ch * 32 + 16));
            *reinterpret_cast<uint4*>(smem + SM_AH + o0) = make_uint4(hw[0], hw[1], hw[2], hw[3]);
            *reinterpret_cast<uint4*>(smem + SM_AH + o1) = make_uint4(hw[4], hw[5], hw[6], hw[7]);
            *reinterpret_cast<uint4*>(smem + SM_AL + o0) = make_uint4(lw[0], lw[1], lw[2], lw[3]);
            *reinterpret_cast<uint4*>(smem + SM_AL + o1) = make_uint4(lw[4], lw[5], lw[6], lw[7]);
        }
        __syncthreads();
    }
}

// ----------------------------------------------------------------------------
extern "C" void kernel_launch(void* const* d_in, const int* in_sizes, int n_in,
                              void* d_out, int out_size) {
    const float* x = (const float*)d_in[0];      // (128, 4, 128, 128) f32
    const float* w = (const float*)d_in[1];      // (2, 6, 3) f32
    float* out = (float*)d_out;                  // (128, 6, 63, 63) f32
    (void)in_sizes; (void)n_in; (void)out_size;

    cudaFuncSetAttribute(qconv_kernel, cudaFuncAttributeMaxDynamicSharedMemorySize, SM_TOTAL);
    build_unitary_kernel<<<4, 256>>>(w);
    qconv_kernel<<<GRID, 256, SM_TOTAL>>>(x, out);
}

// round 6
// speedup vs baseline: 1.4943x; 1.4943x over previous
#include <cuda_runtime.h>
#include <cuda_bf16.h>
#include <cuda_fp16.h>
#include <cstdint>

// ============================================================================
// QConv2D quantum conv via baseline-PTX fp16 mma.sync (HMMA) GEMM.
//   Circuit -> fixed 64x64 complex unitary U (kernel 1, parallel).
//   B[128x64] fp16, rows interleaved: B[2s]=Re U[s,:], B[2s+1]=Im U[s,:].
//   Kernel 2 (CTA = 128 patches): A = raw patch features split fp16 hi/lo,
//   C[128x128] = Ah*B^T + Al*B^T  (fp32 accum; error ~2^-12 from B rounding).
//   Epilogue: probs = C[:,2s]^2 + C[:,2s+1]^2 in-thread, Walsh-signed sums,
//   deferred normalization by ||f||^2.
// ============================================================================

#define N_QUBITS 6
#define OH 63
#define OHW 3969
#define NPATCH (128 * OHW)     // 508032
#define SWZ(o) ((o) ^ (((o) >> 3) & 0x70))

__device__ __half g_B[128 * 64];

__device__ __forceinline__ uint32_t smem_u32(const void* p) {
    uint32_t a;
    asm("{ .reg .u64 t; cvta.to.shared.u64 t, %1; cvt.u32.u64 %0, t; }"
        : "=r"(a) : "l"(p));
    return a;
}
__device__ __forceinline__ void ldmx4(uint32_t* r, uint32_t addr) {
    asm volatile("ldmatrix.sync.aligned.m8n8.x4.shared.b16 {%0,%1,%2,%3}, [%4];"
                 : "=r"(r[0]), "=r"(r[1]), "=r"(r[2]), "=r"(r[3]) : "r"(addr));
}
__device__ __forceinline__ void mma_f16(float* c, const uint32_t* a, const uint32_t* b) {
    asm volatile(
        "mma.sync.aligned.m16n8k16.row.col.f32.f16.f16.f32 "
        "{%0,%1,%2,%3}, {%4,%5,%6,%7}, {%8,%9}, {%0,%1,%2,%3};"
        : "+f"(c[0]), "+f"(c[1]), "+f"(c[2]), "+f"(c[3])
        : "r"(a[0]), "r"(a[1]), "r"(a[2]), "r"(a[3]), "r"(b[0]), "r"(b[1]));
}

// ----------------------------------------------------------------------------
// Kernel 1: build U; emit B interleaved (Re/Im per state) as fp16.
// grid=4, block=256; block handles 16 columns x 16 pair-workers.
// ----------------------------------------------------------------------------
__global__ __launch_bounds__(256) void build_unitary_kernel(const float* __restrict__ w) {
    __shared__ float2 S[16][64];
    __shared__ float gt[12][8];
    int t = threadIdx.x;
    int cl = t >> 4;
    int k  = t & 15;

    if (t < 12) {
        int l = t / 6, q = t % 6;
        float phi   = w[(l * 6 + q) * 3 + 0];
        float theta = w[(l * 6 + q) * 3 + 1];
        float omega = w[(l * 6 + q) * 3 + 2];
        float s2, c2; sincosf(0.5f * theta, &s2, &c2);
        float sap, cap; sincosf(-0.5f * (phi + omega), &sap, &cap);
        float sam, cam; sincosf(-0.5f * (phi - omega), &sam, &cam);
        gt[t][0] =  cap * c2; gt[t][1] =  sap * c2;
        gt[t][2] = -cam * s2; gt[t][3] =  sam * s2;
        gt[t][4] =  cam * s2; gt[t][5] =  sam * s2;
        gt[t][6] =  cap * c2; gt[t][7] = -sap * c2;
    }
    int c = blockIdx.x * 16 + cl;
    #pragma unroll
    for (int i = k; i < 64; i += 16) S[cl][i] = make_float2(i == c ? 1.f : 0.f, 0.f);
    __syncthreads();

    for (int rep = 0; rep < 2; rep++) {
        for (int l = 0; l < 2; l++) {
            for (int q = 0; q < N_QUBITS; q++) {
                const float* g = gt[l * 6 + q];
                float u00x = g[0], u00y = g[1], u01x = g[2], u01y = g[3];
                float u10x = g[4], u10y = g[5], u11x = g[6], u11y = g[7];
                int m = 1 << (5 - q);
                #pragma unroll
                for (int pp = 0; pp < 2; pp++) {
                    int pi = k + pp * 16;
                    int i = ((pi & ~(m - 1)) << 1) | (pi & (m - 1));
                    float2 a = S[cl][i], b = S[cl][i | m];
                    float2 na, nb;
                    na.x = u00x * a.x - u00y * a.y + u01x * b.x - u01y * b.y;
                    na.y = u00x * a.y + u00y * a.x + u01x * b.y + u01y * b.x;
                    nb.x = u10x * a.x - u10y * a.y + u11x * b.x - u11y * b.y;
                    nb.y = u10x * a.y + u10y * a.x + u11x * b.y + u11y * b.x;
                    S[cl][i] = na; S[cl][i | m] = nb;
                }
                __syncthreads();
            }
            int r = (l % (N_QUBITS - 1)) + 1;
            for (int q = 0; q < N_QUBITS; q++) {
                int tq = (q + r) % N_QUBITS;
                int mc = 1 << (5 - q);
                int mt = 1 << (5 - tq);
                int i = 0, kk = k;
                #pragma unroll
                for (int b = 0; b < 6; b++) {
                    int bit = 1 << b;
                    if (bit == mc)      i |= bit;
                    else if (bit == mt) { }
                    else { if (kk & 1) i |= bit; kk >>= 1; }
                }
                float2 tmp = S[cl][i];
                S[cl][i] = S[cl][i | mt];
                S[cl][i | mt] = tmp;
                __syncthreads();
            }
        }
    }
    // B[n][kg]: n = 2s + r, r=0 -> Re U[s][kg], r=1 -> Im U[s][kg]
    for (int it = t; it < 128 * 16; it += 256) {
        int n  = it >> 4;
        int kl = it & 15;
        int s  = n >> 1;
        float v = (n & 1) ? S[kl][s].y : S[kl][s].x;
        int kg = blockIdx.x * 16 + kl;
        g_B[n * 64 + kg] = __float2half(v);
    }
}

// ----------------------------------------------------------------------------
// Kernel 2: HMMA GEMM + epilogue. 256 threads (8 warps, 4x2 tile grid).
// ----------------------------------------------------------------------------
#define SM_AH 0            // 16 KB: 128 rows x 128 B
#define SM_AL 16384        // 16 KB
#define SM_B  32768        // 16 KB
#define SM_SSQ 49152       // float[128] = 512 B
#define SM_SZ  49664       // float[2][128][6] = 6144 B
#define SM_TOTAL 55808

__global__ __launch_bounds__(256, 2)
void qconv_kernel(const float* __restrict__ x, float* __restrict__ out) {
    extern __shared__ char smem[];
    const uint32_t sb = smem_u32(smem);
    float* sSsq = reinterpret_cast<float*>(smem + SM_SSQ);
    float* sZ   = reinterpret_cast<float*>(smem + SM_SZ);   // [ni][row][6]
    const int tid = threadIdx.x;

    // ---- load phase: thread = (patch p = tid>>1, half h = tid&1 -> 2 channels)
    {
        const int p  = tid >> 1;
        const int h  = tid & 1;
        const int pi = blockIdx.x * 128 + p;
        const int b   = pi / OHW;
        const int rem = pi - b * OHW;
        const int oy  = rem / OH;
        const int ox  = rem - oy * OH;
        const float* xb = x + (((b * 4 + 2 * h) * 128) + 2 * oy) * 128 + 2 * ox;

        float ssq = 0.f;
        #pragma unroll
        for (int c2 = 0; c2 < 2; c2++) {
            #pragma unroll
            for (int ky2 = 0; ky2 < 2; ky2++) {
                const float* rA = xb + c2 * 16384 + (2 * ky2) * 128;
                float2 a0 = *reinterpret_cast<const float2*>(rA);
                float2 a1 = *reinterpret_cast<const float2*>(rA + 2);
                float2 b0 = *reinterpret_cast<const float2*>(rA + 128);
                float2 b1 = *reinterpret_cast<const float2*>(rA + 130);
                float v[8] = {a0.x, a0.y, a1.x, a1.y, b0.x, b0.y, b1.x, b1.y};
                uint32_t hw[4], lw[4];
                #pragma unroll
                for (int j = 0; j < 4; j++) {
                    float va = v[2 * j], vb = v[2 * j + 1];
                    ssq += va * va + vb * vb;
                    __half ah = __float2half(va);
                    __half bh = __float2half(vb);
                    __half al = __float2half(va - __half2float(ah));
                    __half bl = __float2half(vb - __half2float(bh));
                    __half2 hp = {ah, bh}, lp = {al, bl};
                    hw[j] = *reinterpret_cast<uint32_t*>(&hp);
                    lw[j] = *reinterpret_cast<uint32_t*>(&lp);
                }
                int chunk = h * 4 + c2 * 2 + ky2;
                uint32_t off = SWZ((uint32_t)(p * 128 + chunk * 16));
                *reinterpret_cast<uint4*>(smem + SM_AH + off) = make_uint4(hw[0], hw[1], hw[2], hw[3]);
                *reinterpret_cast<uint4*>(smem + SM_AL + off) = make_uint4(lw[0], lw[1], lw[2], lw[3]);
            }
        }
        ssq += __shfl_xor_sync(0xffffffffu, ssq, 1);
        if (h == 0) sSsq[p] = ssq;
    }

    // ---- stage B (fp16) with swizzle ----
    {
        const uint4* bsrc = reinterpret_cast<const uint4*>(g_B);
        #pragma unroll
        for (int it = 0; it < 4; it++) {
            int idx = tid + it * 256;
            uint32_t off = SWZ((uint32_t)(idx * 16));
            *reinterpret_cast<uint4*>(smem + SM_B + off) = bsrc[idx];
        }
    }
    __syncthreads();

    // ---- GEMM: warp (mi,ni): rows [32mi,32mi+32), cols [64ni,64ni+64) ----
    const int L   = tid & 31;
    const int wid = tid >> 5;
    const int mi  = wid >> 1;
    const int ni  = wid & 1;
    const int Rm  = mi * 32;
    const int Cn  = ni * 64;
    const int g   = L >> 2;
    const int qd  = L & 3;

    const uint32_t aRow = (uint32_t)(Rm + (L & 7) + (((L >> 3) & 1) << 3));
    const uint32_t aCh  = (L >> 4) & 1;
    const uint32_t bRow = (uint32_t)(Cn + (L & 7) + (((L >> 4) & 1) << 3));
    const uint32_t bCh  = (L >> 3) & 1;

    float acc[2][8][4];
    #pragma unroll
    for (int mt = 0; mt < 2; mt++)
        #pragma unroll
        for (int nt = 0; nt < 8; nt++)
            #pragma unroll
            for (int r = 0; r < 4; r++) acc[mt][nt][r] = 0.f;

    #pragma unroll
    for (int k = 0; k < 4; k++) {
        uint32_t ah[2][4], al[2][4];
        #pragma unroll
        for (int mt = 0; mt < 2; mt++) {
            uint32_t off = SWZ((aRow + mt * 16) * 128 + (2 * k + aCh) * 16);
            ldmx4(ah[mt], sb + SM_AH + off);
            ldmx4(al[mt], sb + SM_AL + off);
        }
        #pragma unroll
        for (int bt = 0; bt < 4; bt++) {
            uint32_t off = SWZ((bRow + bt * 16) * 128 + (2 * k + bCh) * 16);
            uint32_t bf[4];
            ldmx4(bf, sb + SM_B + off);
            #pragma unroll
            for (int mt = 0; mt < 2; mt++)
                #pragma unroll
                for (int n2 = 0; n2 < 2; n2++) {
                    int nt = bt * 2 + n2;
                    mma_f16(acc[mt][nt], ah[mt], bf + 2 * n2);
                    mma_f16(acc[mt][nt], al[mt], bf + 2 * n2);
                }
        }
    }

    // ---- epilogue: per thread 4 rows; state s = 32ni + 4nt + qd ----
    #pragma unroll
    for (int mt = 0; mt < 2; mt++) {
        #pragma unroll
        for (int rh = 0; rh < 2; rh++) {
            float pr[8];
            #pragma unroll
            for (int nt = 0; nt < 8; nt++) {
                float re = acc[mt][nt][rh * 2 + 0];
                float im = acc[mt][nt][rh * 2 + 1];
                pr[nt] = re * re + im * im;
            }
            float qt = 0.f, z1 = 0.f, z2 = 0.f, z3 = 0.f;
            #pragma unroll
            for (int nt = 0; nt < 8; nt++) {
                qt += pr[nt];
                z1 += (nt & 4) ? -pr[nt] : pr[nt];   // qubit1 <-> s bit4
                z2 += (nt & 2) ? -pr[nt] : pr[nt];   // qubit2 <-> s bit3
                z3 += (nt & 1) ? -pr[nt] : pr[nt];   // qubit3 <-> s bit2
            }
            float z0 = qt;                            // qubit0 sign by ni at merge
            float z4 = (qd & 2) ? -qt : qt;           // qubit4 <-> s bit1
            float z5 = (qd & 1) ? -qt : qt;           // qubit5 <-> s bit0
            #pragma unroll
            for (int o = 1; o <= 2; o <<= 1) {
                z0 += __shfl_xor_sync(0xffffffffu, z0, o);
                z1 += __shfl_xor_sync(0xffffffffu, z1, o);
                z2 += __shfl_xor_sync(0xffffffffu, z2, o);
                z3 += __shfl_xor_sync(0xffffffffu, z3, o);
                z4 += __shfl_xor_sync(0xffffffffu, z4, o);
                z5 += __shfl_xor_sync(0xffffffffu, z5, o);
            }
            if (qd == 0) {
                int row = Rm + mt * 16 + rh * 8 + g;
                float* dst = sZ + (ni * 128 + row) * 6;
                dst[0] = z0; dst[1] = z1; dst[2] = z2;
                dst[3] = z3; dst[4] = z4; dst[5] = z5;
            }
        }
    }
    __syncthreads();

    // ---- merge halves + normalize + store ----
    if (tid < 128) {
        const int row = tid;
        const int pi  = blockIdx.x * 128 + row;
        const int b   = pi / OHW;
        const int rem = pi - b * OHW;
        const float inv = 1.f / sSsq[row];
        const float* p0 = sZ + row * 6;
        const float* p1 = sZ + (128 + row) * 6;
        out[(b * 6 + 0) * OHW + rem] = (p0[0] - p1[0]) * inv;
        #pragma unroll
        for (int w = 1; w < 6; w++)
            out[(b * 6 + w) * OHW + rem] = (p0[w] + p1[w]) * inv;
    }
}

// ----------------------------------------------------------------------------
extern "C" void kernel_launch(void* const* d_in, const int* in_sizes, int n_in,
                              void* d_out, int out_size) {
    const float* x = (const float*)d_in[0];      // (128, 4, 128, 128) f32
    const float* w = (const float*)d_in[1];      // (2, 6, 3) f32
    float* out = (float*)d_out;                  // (128, 6, 63, 63) f32
    (void)in_sizes; (void)n_in; (void)out_size;

    cudaFuncSetAttribute(qconv_kernel, cudaFuncAttributeMaxDynamicSharedMemorySize, SM_TOTAL);
    build_unitary_kernel<<<4, 256>>>(w);
    qconv_kernel<<<NPATCH / 128, 256, SM_TOTAL>>>(x, out);
}

// round 7
// speedup vs baseline: 1.6359x; 1.0948x over previous
#include <cuda_runtime.h>
#include <cuda_fp16.h>
#include <cstdint>

// ============================================================================
// QConv2D quantum conv via baseline-PTX fp16 mma.sync (HMMA) GEMM.
//   Kernel 1: build 64x64 unitary U (register statevector, warp per column).
//   B[128x64] fp16, rows interleaved: B[2s]=Re U[s,:], B[2s+1]=Im U[s,:].
//   Kernel 2 (CTA = 128 patches): A = raw patch features split fp16 hi/lo,
//   C[128x128] = Ah*B^T + Al*B^T (fp32 accum). Epilogue: probs, Walsh sums
//   (signed butterfly), deferred normalization by ||f||^2.
// ============================================================================

#define N_QUBITS 6
#define OH 63
#define OHW 3969
#define NPATCH (128 * OHW)     // 508032
#define SWZ(o) ((o) ^ (((o) >> 3) & 0x70))

__device__ __half g_B[128 * 64];

__device__ __forceinline__ uint32_t smem_u32(const void* p) {
    uint32_t a;
    asm("{ .reg .u64 t; cvta.to.shared.u64 t, %1; cvt.u32.u64 %0, t; }"
        : "=r"(a) : "l"(p));
    return a;
}
__device__ __forceinline__ void ldmx4(uint32_t* r, uint32_t addr) {
    asm volatile("ldmatrix.sync.aligned.m8n8.x4.shared.b16 {%0,%1,%2,%3}, [%4];"
                 : "=r"(r[0]), "=r"(r[1]), "=r"(r[2]), "=r"(r[3]) : "r"(addr));
}
__device__ __forceinline__ void mma_f16(float* c, const uint32_t* a, const uint32_t* b) {
    asm volatile(
        "mma.sync.aligned.m16n8k16.row.col.f32.f16.f16.f32 "
        "{%0,%1,%2,%3}, {%4,%5,%6,%7}, {%8,%9}, {%0,%1,%2,%3};"
        : "+f"(c[0]), "+f"(c[1]), "+f"(c[2]), "+f"(c[3])
        : "r"(a[0]), "r"(a[1]), "r"(a[2]), "r"(a[3]), "r"(b[0]), "r"(b[1]));
}
__device__ __forceinline__ float2 cmad(float2 u, float2 a, float2 v, float2 b) {
    // u*a + v*b (complex)
    float2 r;
    r.x = u.x * a.x - u.y * a.y + v.x * b.x - v.y * b.y;
    r.y = u.x * a.y + u.y * a.x + v.x * b.y + v.y * b.x;
    return r;
}

// ----------------------------------------------------------------------------
// Kernel 1: build U. One warp per column; lane holds states 2L, 2L+1.
// grid=8, block=256 (8 warps) -> 64 columns. No __syncthreads in gate loop.
// ----------------------------------------------------------------------------
__global__ __launch_bounds__(256) void build_unitary_kernel(const float* __restrict__ w) {
    __shared__ float gt[12][8];
    const int t = threadIdx.x;
    if (t < 12) {
        int l = t / 6, q = t % 6;
        float phi   = w[(l * 6 + q) * 3 + 0];
        float theta = w[(l * 6 + q) * 3 + 1];
        float omega = w[(l * 6 + q) * 3 + 2];
        float s2, c2; sincosf(0.5f * theta, &s2, &c2);
        float sap, cap; sincosf(-0.5f * (phi + omega), &sap, &cap);
        float sam, cam; sincosf(-0.5f * (phi - omega), &sam, &cam);
        gt[t][0] =  cap * c2; gt[t][1] =  sap * c2;   // u00
        gt[t][2] = -cam * s2; gt[t][3] =  sam * s2;   // u01
        gt[t][4] =  cam * s2; gt[t][5] =  sam * s2;   // u10
        gt[t][6] =  cap * c2; gt[t][7] = -sap * c2;   // u11
    }
    __syncthreads();

    const int lane = t & 31;
    const int col  = blockIdx.x * 8 + (t >> 5);

    float2 s0 = make_float2((2 * lane     == col) ? 1.f : 0.f, 0.f);
    float2 s1 = make_float2((2 * lane + 1 == col) ? 1.f : 0.f, 0.f);

    for (int rep = 0; rep < 2; rep++) {
        for (int l = 0; l < 2; l++) {
            // 6 rotations
            for (int q = 0; q < N_QUBITS; q++) {
                const float* g = gt[l * 6 + q];
                float2 u00 = {g[0], g[1]}, u01 = {g[2], g[3]};
                float2 u10 = {g[4], g[5]}, u11 = {g[6], g[7]};
                int m = 1 << (5 - q);
                if (m == 1) {
                    float2 a = s0, b = s1;
                    s0 = cmad(u00, a, u01, b);
                    s1 = cmad(u10, a, u11, b);
                } else {
                    int d = m >> 1;
                    float2 p0, p1;
                    p0.x = __shfl_xor_sync(0xffffffffu, s0.x, d);
                    p0.y = __shfl_xor_sync(0xffffffffu, s0.y, d);
                    p1.x = __shfl_xor_sync(0xffffffffu, s1.x, d);
                    p1.y = __shfl_xor_sync(0xffffffffu, s1.y, d);
                    if (lane & d) {
                        s0 = cmad(u10, p0, u11, s0);
                        s1 = cmad(u10, p1, u11, s1);
                    } else {
                        s0 = cmad(u00, s0, u01, p0);
                        s1 = cmad(u00, s1, u01, p1);
                    }
                }
            }
            // ring of CNOTs, range r = l+1
            int r = l + 1;
            for (int q = 0; q < N_QUBITS; q++) {
                int tq = (q + r) % N_QUBITS;
                int mc = 1 << (5 - q);
                int mt = 1 << (5 - tq);
                if (mt == 1) {
                    if (lane & (mc >> 1)) { float2 tmp = s0; s0 = s1; s1 = tmp; }
                } else {
                    int d = mt >> 1;
                    if (mc == 1) {
                        float2 t1;
                        t1.x = __shfl_xor_sync(0xffffffffu, s1.x, d);
                        t1.y = __shfl_xor_sync(0xffffffffu, s1.y, d);
                        s1 = t1;
                    } else {
                        float2 t0, t1;
                        t0.x = __shfl_xor_sync(0xffffffffu, s0.x, d);
                        t0.y = __shfl_xor_sync(0xffffffffu, s0.y, d);
                        t1.x = __shfl_xor_sync(0xffffffffu, s1.x, d);
                        t1.y = __shfl_xor_sync(0xffffffffu, s1.y, d);
                        if (lane & (mc >> 1)) { s0 = t0; s1 = t1; }
                    }
                }
            }
        }
    }
    // B rows: n = 2s + (0:Re, 1:Im); s0 -> n = 4L, 4L+1; s1 -> 4L+2, 4L+3
    g_B[(4 * lane + 0) * 64 + col] = __float2half(s0.x);
    g_B[(4 * lane + 1) * 64 + col] = __float2half(s0.y);
    g_B[(4 * lane + 2) * 64 + col] = __float2half(s1.x);
    g_B[(4 * lane + 3) * 64 + col] = __float2half(s1.y);
}

// ----------------------------------------------------------------------------
// Kernel 2: HMMA GEMM + epilogue. 256 threads (8 warps, 4x2 tile grid).
// ----------------------------------------------------------------------------
#define SM_AH 0            // 16 KB: 128 rows x 128 B
#define SM_AL 16384        // 16 KB
#define SM_B  32768        // 16 KB
#define SM_SSQ 49152       // float[128] = 512 B
#define SM_SZ  49664       // float[2][128][6] = 6144 B
#define SM_TOTAL 55808

__global__ __launch_bounds__(256, 2)
void qconv_kernel(const float* __restrict__ x, float* __restrict__ out) {
    extern __shared__ char smem[];
    const uint32_t sb = smem_u32(smem);
    float* sSsq = reinterpret_cast<float*>(smem + SM_SSQ);
    float* sZ   = reinterpret_cast<float*>(smem + SM_SZ);   // [ni][row][6]
    const int tid = threadIdx.x;

    // ---- B gmem loads first (latency overlaps x gather) ----
    uint4 breg[4];
    {
        const uint4* bsrc = reinterpret_cast<const uint4*>(g_B);
        #pragma unroll
        for (int it = 0; it < 4; it++) breg[it] = bsrc[tid + it * 256];
    }

    // ---- load phase: thread = (patch p = tid>>1, half h = tid&1 -> 2 channels)
    {
        const int p  = tid >> 1;
        const int h  = tid & 1;
        const int pi = blockIdx.x * 128 + p;
        const int b   = pi / OHW;
        const int rem = pi - b * OHW;
        const int oy  = rem / OH;
        const int ox  = rem - oy * OH;
        const float* xb = x + (((b * 4 + 2 * h) * 128) + 2 * oy) * 128 + 2 * ox;

        float ssq = 0.f;
        #pragma unroll
        for (int c2 = 0; c2 < 2; c2++) {
            #pragma unroll
            for (int ky2 = 0; ky2 < 2; ky2++) {
                const float* rA = xb + c2 * 16384 + (2 * ky2) * 128;
                float2 P[4];
                P[0] = *reinterpret_cast<const float2*>(rA);
                P[1] = *reinterpret_cast<const float2*>(rA + 2);
                P[2] = *reinterpret_cast<const float2*>(rA + 128);
                P[3] = *reinterpret_cast<const float2*>(rA + 130);
                uint32_t hw[4], lw[4];
                #pragma unroll
                for (int j = 0; j < 4; j++) {
                    ssq += P[j].x * P[j].x + P[j].y * P[j].y;
                    __half2 h2 = __float22half2_rn(P[j]);
                    float2 bk = __half22float2(h2);
                    __half2 l2 = __float22half2_rn(make_float2(P[j].x - bk.x, P[j].y - bk.y));
                    hw[j] = *reinterpret_cast<uint32_t*>(&h2);
                    lw[j] = *reinterpret_cast<uint32_t*>(&l2);
                }
                int chunk = h * 4 + c2 * 2 + ky2;
                uint32_t off = SWZ((uint32_t)(p * 128 + chunk * 16));
                *reinterpret_cast<uint4*>(smem + SM_AH + off) = make_uint4(hw[0], hw[1], hw[2], hw[3]);
                *reinterpret_cast<uint4*>(smem + SM_AL + off) = make_uint4(lw[0], lw[1], lw[2], lw[3]);
            }
        }
        ssq += __shfl_xor_sync(0xffffffffu, ssq, 1);
        if (h == 0) sSsq[p] = ssq;
    }

    // ---- stage B (fp16) with swizzle ----
    {
        #pragma unroll
        for (int it = 0; it < 4; it++) {
            uint32_t off = SWZ((uint32_t)((tid + it * 256) * 16));
            *reinterpret_cast<uint4*>(smem + SM_B + off) = breg[it];
        }
    }
    __syncthreads();

    // ---- GEMM: warp (mi,ni): rows [32mi,32mi+32), cols [64ni,64ni+64) ----
    const int L   = tid & 31;
    const int wid = tid >> 5;
    const int mi  = wid >> 1;
    const int ni  = wid & 1;
    const int Rm  = mi * 32;
    const int Cn  = ni * 64;
    const int g   = L >> 2;
    const int qd  = L & 3;

    const uint32_t aRow = (uint32_t)(Rm + (L & 7) + (((L >> 3) & 1) << 3));
    const uint32_t aCh  = (L >> 4) & 1;
    const uint32_t bRow = (uint32_t)(Cn + (L & 7) + (((L >> 4) & 1) << 3));
    const uint32_t bCh  = (L >> 3) & 1;

    float acc[2][8][4];
    #pragma unroll
    for (int mt = 0; mt < 2; mt++)
        #pragma unroll
        for (int nt = 0; nt < 8; nt++)
            #pragma unroll
            for (int r = 0; r < 4; r++) acc[mt][nt][r] = 0.f;

    #pragma unroll
    for (int k = 0; k < 4; k++) {
        uint32_t ah[2][4], al[2][4];
        #pragma unroll
        for (int mt = 0; mt < 2; mt++) {
            uint32_t off = SWZ((aRow + mt * 16) * 128 + (2 * k + aCh) * 16);
            ldmx4(ah[mt], sb + SM_AH + off);
            ldmx4(al[mt], sb + SM_AL + off);
        }
        #pragma unroll
        for (int bt = 0; bt < 4; bt++) {
            uint32_t off = SWZ((bRow + bt * 16) * 128 + (2 * k + bCh) * 16);
            uint32_t bf[4];
            ldmx4(bf, sb + SM_B + off);
            #pragma unroll
            for (int mt = 0; mt < 2; mt++)
                #pragma unroll
                for (int n2 = 0; n2 < 2; n2++) {
                    int nt = bt * 2 + n2;
                    mma_f16(acc[mt][nt], ah[mt], bf + 2 * n2);
                    mma_f16(acc[mt][nt], al[mt], bf + 2 * n2);
                }
        }
    }

    // ---- epilogue: per thread 4 rows; state s = 32ni + 4nt + qd ----
    #pragma unroll
    for (int mt = 0; mt < 2; mt++) {
        #pragma unroll
        for (int rh = 0; rh < 2; rh++) {
            float pr[8];
            #pragma unroll
            for (int nt = 0; nt < 8; nt++) {
                float re = acc[mt][nt][rh * 2 + 0];
                float im = acc[mt][nt][rh * 2 + 1];
                pr[nt] = re * re + im * im;
            }
            float qt = 0.f, z1 = 0.f, z2 = 0.f, z3 = 0.f;
            #pragma unroll
            for (int nt = 0; nt < 8; nt++) {
                qt += pr[nt];
                z1 += (nt & 4) ? -pr[nt] : pr[nt];   // qubit1 <-> s bit4
                z2 += (nt & 2) ? -pr[nt] : pr[nt];   // qubit2 <-> s bit3
                z3 += (nt & 1) ? -pr[nt] : pr[nt];   // qubit3 <-> s bit2
            }
            // signed 4-pt Walsh butterfly over the quad:
            // lane qd=0 -> z0 partial, qd=1 -> z5 partial, qd=2 -> z4 partial
            float W = qt;
            #pragma unroll
            for (int m = 1; m <= 2; m <<= 1) {
                float tt = __shfl_xor_sync(0xffffffffu, W, m);
                W = (L & m) ? (tt - W) : (W + tt);
            }
            z1 += __shfl_xor_sync(0xffffffffu, z1, 1);
            z1 += __shfl_xor_sync(0xffffffffu, z1, 2);
            z2 += __shfl_xor_sync(0xffffffffu, z2, 1);
            z2 += __shfl_xor_sync(0xffffffffu, z2, 2);
            z3 += __shfl_xor_sync(0xffffffffu, z3, 1);
            z3 += __shfl_xor_sync(0xffffffffu, z3, 2);

            int row = Rm + mt * 16 + rh * 8 + g;
            float* dst = sZ + (ni * 128 + row) * 6;
            if (qd == 0) { dst[0] = W; dst[1] = z1; dst[2] = z2; dst[3] = z3; }
            else if (qd == 1) dst[5] = W;
            else if (qd == 2) dst[4] = W;
        }
    }
    __syncthreads();

    // ---- merge halves + normalize + store ----
    if (tid < 128) {
        const int row = tid;
        const int pi  = blockIdx.x * 128 + row;
        const int b   = pi / OHW;
        const int rem = pi - b * OHW;
        const float inv = 1.f / sSsq[row];
        const float* p0 = sZ + row * 6;
        const float* p1 = sZ + (128 + row) * 6;
        out[(b * 6 + 0) * OHW + rem] = (p0[0] - p1[0]) * inv;
        #pragma unroll
        for (int w = 1; w < 6; w++)
            out[(b * 6 + w) * OHW + rem] = (p0[w] + p1[w]) * inv;
    }
}

// ----------------------------------------------------------------------------
extern "C" void kernel_launch(void* const* d_in, const int* in_sizes, int n_in,
                              void* d_out, int out_size) {
    const float* x = (const float*)d_in[0];      // (128, 4, 128, 128) f32
    const float* w = (const float*)d_in[1];      // (2, 6, 3) f32
    float* out = (float*)d_out;                  // (128, 6, 63, 63) f32
    (void)in_sizes; (void)n_in; (void)out_size;

    cudaFuncSetAttribute(qconv_kernel, cudaFuncAttributeMaxDynamicSharedMemorySize, SM_TOTAL);
    build_unitary_kernel<<<8, 256>>>(w);
    qconv_kernel<<<NPATCH / 128, 256, SM_TOTAL>>>(x, out);
}

// round 8
// speedup vs baseline: 1.9633x; 1.2001x over previous
#include <cuda_runtime.h>
#include <cuda_fp16.h>
#include <cstdint>

// ============================================================================
// QConv2D quantum conv via baseline-PTX fp16 mma.sync (HMMA) GEMM.
//   Kernel 1: build 64x64 unitary U (register statevector, warp per column).
//   B[128x64] fp16, rows interleaved: B[2s]=Re U[s,:], B[2s+1]=Im U[s,:].
//   Kernel 2 (CTA = 128 patches): A = patch features fp16 (single precision
//   term: C[128x128] = A*B^T, fp32 accum; error ~2^-12 from A+B rounding).
//   Epilogue: probs = C[:,2s]^2 + C[:,2s+1]^2, Walsh-signed sums (butterfly),
//   deferred normalization by ||f||^2.
// ============================================================================

#define N_QUBITS 6
#define OH 63
#define OHW 3969
#define NPATCH (128 * OHW)     // 508032
#define SWZ(o) ((o) ^ (((o) >> 3) & 0x70))

__device__ __half g_B[128 * 64];

__device__ __forceinline__ uint32_t smem_u32(const void* p) {
    uint32_t a;
    asm("{ .reg .u64 t; cvta.to.shared.u64 t, %1; cvt.u32.u64 %0, t; }"
        : "=r"(a) : "l"(p));
    return a;
}
__device__ __forceinline__ void ldmx4(uint32_t* r, uint32_t addr) {
    asm volatile("ldmatrix.sync.aligned.m8n8.x4.shared.b16 {%0,%1,%2,%3}, [%4];"
                 : "=r"(r[0]), "=r"(r[1]), "=r"(r[2]), "=r"(r[3]) : "r"(addr));
}
__device__ __forceinline__ void mma_f16(float* c, const uint32_t* a, const uint32_t* b) {
    asm volatile(
        "mma.sync.aligned.m16n8k16.row.col.f32.f16.f16.f32 "
        "{%0,%1,%2,%3}, {%4,%5,%6,%7}, {%8,%9}, {%0,%1,%2,%3};"
        : "+f"(c[0]), "+f"(c[1]), "+f"(c[2]), "+f"(c[3])
        : "r"(a[0]), "r"(a[1]), "r"(a[2]), "r"(a[3]), "r"(b[0]), "r"(b[1]));
}
__device__ __forceinline__ float2 cmad(float2 u, float2 a, float2 v, float2 b) {
    float2 r;
    r.x = u.x * a.x - u.y * a.y + v.x * b.x - v.y * b.y;
    r.y = u.x * a.y + u.y * a.x + v.x * b.y + v.y * b.x;
    return r;
}

// ----------------------------------------------------------------------------
// Kernel 1: build U. One warp per column; lane holds states 2L, 2L+1.
// grid=8, block=256 (8 warps) -> 64 columns.
// ----------------------------------------------------------------------------
__global__ __launch_bounds__(256) void build_unitary_kernel(const float* __restrict__ w) {
    __shared__ float gt[12][8];
    const int t = threadIdx.x;
    if (t < 12) {
        int l = t / 6, q = t % 6;
        float phi   = w[(l * 6 + q) * 3 + 0];
        float theta = w[(l * 6 + q) * 3 + 1];
        float omega = w[(l * 6 + q) * 3 + 2];
        float s2, c2; sincosf(0.5f * theta, &s2, &c2);
        float sap, cap; sincosf(-0.5f * (phi + omega), &sap, &cap);
        float sam, cam; sincosf(-0.5f * (phi - omega), &sam, &cam);
        gt[t][0] =  cap * c2; gt[t][1] =  sap * c2;   // u00
        gt[t][2] = -cam * s2; gt[t][3] =  sam * s2;   // u01
        gt[t][4] =  cam * s2; gt[t][5] =  sam * s2;   // u10
        gt[t][6] =  cap * c2; gt[t][7] = -sap * c2;   // u11
    }
    __syncthreads();

    const int lane = t & 31;
    const int col  = blockIdx.x * 8 + (t >> 5);

    float2 s0 = make_float2((2 * lane     == col) ? 1.f : 0.f, 0.f);
    float2 s1 = make_float2((2 * lane + 1 == col) ? 1.f : 0.f, 0.f);

    for (int rep = 0; rep < 2; rep++) {
        for (int l = 0; l < 2; l++) {
            for (int q = 0; q < N_QUBITS; q++) {
                const float* g = gt[l * 6 + q];
                float2 u00 = {g[0], g[1]}, u01 = {g[2], g[3]};
                float2 u10 = {g[4], g[5]}, u11 = {g[6], g[7]};
                int m = 1 << (5 - q);
                if (m == 1) {
                    float2 a = s0, b = s1;
                    s0 = cmad(u00, a, u01, b);
                    s1 = cmad(u10, a, u11, b);
                } else {
                    int d = m >> 1;
                    float2 p0, p1;
                    p0.x = __shfl_xor_sync(0xffffffffu, s0.x, d);
                    p0.y = __shfl_xor_sync(0xffffffffu, s0.y, d);
                    p1.x = __shfl_xor_sync(0xffffffffu, s1.x, d);
                    p1.y = __shfl_xor_sync(0xffffffffu, s1.y, d);
                    if (lane & d) {
                        s0 = cmad(u10, p0, u11, s0);
                        s1 = cmad(u10, p1, u11, s1);
                    } else {
                        s0 = cmad(u00, s0, u01, p0);
                        s1 = cmad(u00, s1, u01, p1);
                    }
                }
            }
            int r = l + 1;
            for (int q = 0; q < N_QUBITS; q++) {
                int tq = (q + r) % N_QUBITS;
                int mc = 1 << (5 - q);
                int mt = 1 << (5 - tq);
                if (mt == 1) {
                    if (lane & (mc >> 1)) { float2 tmp = s0; s0 = s1; s1 = tmp; }
                } else {
                    int d = mt >> 1;
                    if (mc == 1) {
                        float2 t1;
                        t1.x = __shfl_xor_sync(0xffffffffu, s1.x, d);
                        t1.y = __shfl_xor_sync(0xffffffffu, s1.y, d);
                        s1 = t1;
                    } else {
                        float2 t0, t1;
                        t0.x = __shfl_xor_sync(0xffffffffu, s0.x, d);
                        t0.y = __shfl_xor_sync(0xffffffffu, s0.y, d);
                        t1.x = __shfl_xor_sync(0xffffffffu, s1.x, d);
                        t1.y = __shfl_xor_sync(0xffffffffu, s1.y, d);
                        if (lane & (mc >> 1)) { s0 = t0; s1 = t1; }
                    }
                }
            }
        }
    }
    g_B[(4 * lane + 0) * 64 + col] = __float2half(s0.x);
    g_B[(4 * lane + 1) * 64 + col] = __float2half(s0.y);
    g_B[(4 * lane + 2) * 64 + col] = __float2half(s1.x);
    g_B[(4 * lane + 3) * 64 + col] = __float2half(s1.y);
}

// ----------------------------------------------------------------------------
// Kernel 2: HMMA GEMM + epilogue. 256 threads (8 warps, 4x2 tile grid).
// ----------------------------------------------------------------------------
#define SM_A  0            // 16 KB: 128 rows x 128 B
#define SM_B  16384        // 16 KB
#define SM_SSQ 32768       // float[128] = 512 B
#define SM_SZ  33280       // float[2][128][6] = 6144 B
#define SM_TOTAL 39424

__global__ __launch_bounds__(256, 2)
void qconv_kernel(const float* __restrict__ x, float* __restrict__ out) {
    extern __shared__ char smem[];
    const uint32_t sb = smem_u32(smem);
    float* sSsq = reinterpret_cast<float*>(smem + SM_SSQ);
    float* sZ   = reinterpret_cast<float*>(smem + SM_SZ);   // [ni][row][6]
    const int tid = threadIdx.x;

    // ---- B gmem loads first (latency overlaps x gather) ----
    uint4 breg[4];
    {
        const uint4* bsrc = reinterpret_cast<const uint4*>(g_B);
        #pragma unroll
        for (int it = 0; it < 4; it++) breg[it] = bsrc[tid + it * 256];
    }

    // ---- load phase: thread = (patch p = tid>>1, half h = tid&1 -> 2 channels)
    {
        const int p  = tid >> 1;
        const int h  = tid & 1;
        const int pi = blockIdx.x * 128 + p;
        const int b   = pi / OHW;
        const int rem = pi - b * OHW;
        const int oy  = rem / OH;
        const int ox  = rem - oy * OH;
        const float* xb = x + (((b * 4 + 2 * h) * 128) + 2 * oy) * 128 + 2 * ox;

        float ssq = 0.f;
        #pragma unroll
        for (int c2 = 0; c2 < 2; c2++) {
            #pragma unroll
            for (int ky2 = 0; ky2 < 2; ky2++) {
                const float* rA = xb + c2 * 16384 + (2 * ky2) * 128;
                float2 P[4];
                P[0] = *reinterpret_cast<const float2*>(rA);
                P[1] = *reinterpret_cast<const float2*>(rA + 2);
                P[2] = *reinterpret_cast<const float2*>(rA + 128);
                P[3] = *reinterpret_cast<const float2*>(rA + 130);
                uint32_t hw[4];
                #pragma unroll
                for (int j = 0; j < 4; j++) {
                    ssq += P[j].x * P[j].x + P[j].y * P[j].y;
                    __half2 h2 = __float22half2_rn(P[j]);
                    hw[j] = *reinterpret_cast<uint32_t*>(&h2);
                }
                int chunk = h * 4 + c2 * 2 + ky2;
                uint32_t off = SWZ((uint32_t)(p * 128 + chunk * 16));
                *reinterpret_cast<uint4*>(smem + SM_A + off) = make_uint4(hw[0], hw[1], hw[2], hw[3]);
            }
        }
        ssq += __shfl_xor_sync(0xffffffffu, ssq, 1);
        if (h == 0) sSsq[p] = ssq;
    }

    // ---- stage B (fp16) with swizzle ----
    {
        #pragma unroll
        for (int it = 0; it < 4; it++) {
            uint32_t off = SWZ((uint32_t)((tid + it * 256) * 16));
            *reinterpret_cast<uint4*>(smem + SM_B + off) = breg[it];
        }
    }
    __syncthreads();

    // ---- GEMM: warp (mi,ni): rows [32mi,32mi+32), cols [64ni,64ni+64) ----
    const int L   = tid & 31;
    const int wid = tid >> 5;
    const int mi  = wid >> 1;
    const int ni  = wid & 1;
    const int Rm  = mi * 32;
    const int Cn  = ni * 64;
    const int g   = L >> 2;
    const int qd  = L & 3;

    const uint32_t aRow = (uint32_t)(Rm + (L & 7) + (((L >> 3) & 1) << 3));
    const uint32_t aCh  = (L >> 4) & 1;
    const uint32_t bRow = (uint32_t)(Cn + (L & 7) + (((L >> 4) & 1) << 3));
    const uint32_t bCh  = (L >> 3) & 1;

    float acc[2][8][4];
    #pragma unroll
    for (int mt = 0; mt < 2; mt++)
        #pragma unroll
        for (int nt = 0; nt < 8; nt++)
            #pragma unroll
            for (int r = 0; r < 4; r++) acc[mt][nt][r] = 0.f;

    #pragma unroll
    for (int k = 0; k < 4; k++) {
        uint32_t ah[2][4];
        #pragma unroll
        for (int mt = 0; mt < 2; mt++) {
            uint32_t off = SWZ((aRow + mt * 16) * 128 + (2 * k + aCh) * 16);
            ldmx4(ah[mt], sb + SM_A + off);
        }
        #pragma unroll
        for (int bt = 0; bt < 4; bt++) {
            uint32_t off = SWZ((bRow + bt * 16) * 128 + (2 * k + bCh) * 16);
            uint32_t bf[4];
            ldmx4(bf, sb + SM_B + off);
            #pragma unroll
            for (int mt = 0; mt < 2; mt++)
                #pragma unroll
                for (int n2 = 0; n2 < 2; n2++) {
                    int nt = bt * 2 + n2;
                    mma_f16(acc[mt][nt], ah[mt], bf + 2 * n2);
                }
        }
    }

    // ---- epilogue: per thread 4 rows; state s = 32ni + 4nt + qd ----
    #pragma unroll
    for (int mt = 0; mt < 2; mt++) {
        #pragma unroll
        for (int rh = 0; rh < 2; rh++) {
            float pr[8];
            #pragma unroll
            for (int nt = 0; nt < 8; nt++) {
                float re = acc[mt][nt][rh * 2 + 0];
                float im = acc[mt][nt][rh * 2 + 1];
                pr[nt] = re * re + im * im;
            }
            float qt = 0.f, z1 = 0.f, z2 = 0.f, z3 = 0.f;
            #pragma unroll
            for (int nt = 0; nt < 8; nt++) {
                qt += pr[nt];
                z1 += (nt & 4) ? -pr[nt] : pr[nt];   // qubit1 <-> s bit4
                z2 += (nt & 2) ? -pr[nt] : pr[nt];   // qubit2 <-> s bit3
                z3 += (nt & 1) ? -pr[nt] : pr[nt];   // qubit3 <-> s bit2
            }
            // signed 4-pt Walsh butterfly over the quad:
            float W = qt;
            #pragma unroll
            for (int m = 1; m <= 2; m <<= 1) {
                float tt = __shfl_xor_sync(0xffffffffu, W, m);
                W = (L & m) ? (tt - W) : (W + tt);
            }
            z1 += __shfl_xor_sync(0xffffffffu, z1, 1);
            z1 += __shfl_xor_sync(0xffffffffu, z1, 2);
            z2 += __shfl_xor_sync(0xffffffffu, z2, 1);
            z2 += __shfl_xor_sync(0xffffffffu, z2, 2);
            z3 += __shfl_xor_sync(0xffffffffu, z3, 1);
            z3 += __shfl_xor_sync(0xffffffffu, z3, 2);

            int row = Rm + mt * 16 + rh * 8 + g;
            float* dst = sZ + (ni * 128 + row) * 6;
            if (qd == 0) { dst[0] = W; dst[1] = z1; dst[2] = z2; dst[3] = z3; }
            else if (qd == 1) dst[5] = W;
            else if (qd == 2) dst[4] = W;
        }
    }
    __syncthreads();

    // ---- merge halves + normalize + store ----
    if (tid < 128) {
        const int row = tid;
        const int pi  = blockIdx.x * 128 + row;
        const int b   = pi / OHW;
        const int rem = pi - b * OHW;
        const float inv = 1.f / sSsq[row];
        const float* p0 = sZ + row * 6;
        const float* p1 = sZ + (128 + row) * 6;
        out[(b * 6 + 0) * OHW + rem] = (p0[0] - p1[0]) * inv;
        #pragma unroll
        for (int w = 1; w < 6; w++)
            out[(b * 6 + w) * OHW + rem] = (p0[w] + p1[w]) * inv;
    }
}

// ----------------------------------------------------------------------------
extern "C" void kernel_launch(void* const* d_in, const int* in_sizes, int n_in,
                              void* d_out, int out_size) {
    const float* x = (const float*)d_in[0];      // (128, 4, 128, 128) f32
    const float* w = (const float*)d_in[1];      // (2, 6, 3) f32
    float* out = (float*)d_out;                  // (128, 6, 63, 63) f32
    (void)in_sizes; (void)n_in; (void)out_size;

    cudaFuncSetAttribute(qconv_kernel, cudaFuncAttributeMaxDynamicSharedMemorySize, SM_TOTAL);
    build_unitary_kernel<<<8, 256>>>(w);
    qconv_kernel<<<NPATCH / 128, 256, SM_TOTAL>>>(x, out);
}